// round 2
// baseline (speedup 1.0000x reference)
#include <cuda_runtime.h>

// out = noised + 0.1f * noise over 50,331,648 fp32 (12,582,912 float4).
// HBM-bound. 4 float4 per thread, loads front-batched (MLP_p1 = 8) to hide
// DRAM latency; block-strided addressing keeps LDG.128 fully coalesced.

#define VPT 4  // float4 vectors per thread

__global__ void __launch_bounds__(256) gnoise_kernel(
    const float4* __restrict__ noised,
    const float4* __restrict__ noise,
    float4* __restrict__ out,
    int n4)
{
    // Each block owns a contiguous chunk of 256*VPT vectors.
    int base = blockIdx.x * (256 * VPT) + threadIdx.x;

    float4 a[VPT], b[VPT];

    if (base + 256 * (VPT - 1) < n4) {
        // Fast path: all VPT vectors in range. Front-batch all loads.
#pragma unroll
        for (int k = 0; k < VPT; k++) a[k] = noised[base + 256 * k];
#pragma unroll
        for (int k = 0; k < VPT; k++) b[k] = noise[base + 256 * k];
#pragma unroll
        for (int k = 0; k < VPT; k++) {
            float4 r;
            r.x = fmaf(0.1f, b[k].x, a[k].x);
            r.y = fmaf(0.1f, b[k].y, a[k].y);
            r.z = fmaf(0.1f, b[k].z, a[k].z);
            r.w = fmaf(0.1f, b[k].w, a[k].w);
            out[base + 256 * k] = r;
        }
    } else {
        // Boundary blocks: per-vector guard.
#pragma unroll
        for (int k = 0; k < VPT; k++) {
            int i = base + 256 * k;
            if (i < n4) {
                float4 av = noised[i];
                float4 bv = noise[i];
                float4 r;
                r.x = fmaf(0.1f, bv.x, av.x);
                r.y = fmaf(0.1f, bv.y, av.y);
                r.z = fmaf(0.1f, bv.z, av.z);
                r.w = fmaf(0.1f, bv.w, av.w);
                out[i] = r;
            }
        }
    }
}

// Scalar tail for n % 4 != 0 (not hit for this shape, kept for safety).
__global__ void gnoise_tail(
    const float* __restrict__ noised,
    const float* __restrict__ noise,
    float* __restrict__ out,
    int start, int n)
{
    int i = start + blockIdx.x * blockDim.x + threadIdx.x;
    if (i < n) {
        out[i] = fmaf(0.1f, noise[i], noised[i]);
    }
}

extern "C" void kernel_launch(void* const* d_in, const int* in_sizes, int n_in,
                              void* d_out, int out_size)
{
    const float* noised = (const float*)d_in[0];
    const float* noise  = (const float*)d_in[1];
    float* out = (float*)d_out;
    int n = in_sizes[0];

    int n4 = n / 4;
    if (n4 > 0) {
        const int threads = 256;
        const int vec_per_block = threads * VPT;
        int blocks = (n4 + vec_per_block - 1) / vec_per_block;
        gnoise_kernel<<<blocks, threads>>>(
            (const float4*)noised, (const float4*)noise, (float4*)out, n4);
    }
    int rem = n - n4 * 4;
    if (rem > 0) {
        gnoise_tail<<<1, 32>>>(noised, noise, out, n4 * 4, n);
    }
}

// round 4
// speedup vs baseline: 1.0225x; 1.0225x over previous
#include <cuda_runtime.h>

// out = noised + 0.1f * noise over 50,331,648 fp32 (12,582,912 float4).
// Pure HBM stream, zero reuse: R1 structure (1 float4/thread, low regs,
// high occupancy) + streaming cache hints (__ldcs/__stcs) so the one-pass
// 604MB stream doesn't thrash L1/L2.

__global__ void __launch_bounds__(256) gnoise_kernel(
    const float4* __restrict__ noised,
    const float4* __restrict__ noise,
    float4* __restrict__ out,
    int n4)
{
    int i = blockIdx.x * blockDim.x + threadIdx.x;
    if (i < n4) {
        float4 a = __ldcs(noised + i);
        float4 b = __ldcs(noise + i);
        float4 r;
        r.x = fmaf(0.1f, b.x, a.x);
        r.y = fmaf(0.1f, b.y, a.y);
        r.z = fmaf(0.1f, b.z, a.z);
        r.w = fmaf(0.1f, b.w, a.w);
        __stcs(out + i, r);
    }
}

// Scalar tail for n % 4 != 0 (not hit for this shape, kept for safety).
__global__ void gnoise_tail(
    const float* __restrict__ noised,
    const float* __restrict__ noise,
    float* __restrict__ out,
    int start, int n)
{
    int i = start + blockIdx.x * blockDim.x + threadIdx.x;
    if (i < n) {
        out[i] = fmaf(0.1f, noise[i], noised[i]);
    }
}

extern "C" void kernel_launch(void* const* d_in, const int* in_sizes, int n_in,
                              void* d_out, int out_size)
{
    const float* noised = (const float*)d_in[0];
    const float* noise  = (const float*)d_in[1];
    float* out = (float*)d_out;
    int n = in_sizes[0];

    int n4 = n / 4;
    if (n4 > 0) {
        const int threads = 256;
        int blocks = (n4 + threads - 1) / threads;
        gnoise_kernel<<<blocks, threads>>>(
            (const float4*)noised, (const float4*)noise, (float4*)out, n4);
    }
    int rem = n - n4 * 4;
    if (rem > 0) {
        gnoise_tail<<<1, 32>>>(noised, noise, out, n4 * 4, n);
    }
}